// round 1
// baseline (speedup 1.0000x reference)
#include <cuda_runtime.h>
#include <math.h>

// ---------------- problem constants ----------------
// B=16, P=512, S=1024, D=1024, H_FULL=16 (hd=64), H_LIGHT=8 (hd=128)
// M_P = B*P = 8192, M_S = B*S = 16384

// ---------------- device scratch (no allocs allowed) ----------------
__device__ float g_q     [8192u  * 1024u];   // cross Q             [B*P, D]
__device__ float g_kv    [16384u * 2048u];   // cross K|V           [B*S, 2D]
__device__ float g_qkv   [8192u  * 3072u];   // self/light QKV      [B*P, 3D]
__device__ float g_sc    [134217728u];       // scores (max B*H*P*S)
__device__ float g_ob    [8192u  * 1024u];   // attn output (pre out-proj)
__device__ float g_rw    [8192u  * 1024u];   // out-proj result
__device__ float g_cross [8192u  * 1024u];
__device__ float g_selfo [8192u  * 1024u];
__device__ float g_light [8192u  * 1024u];
__device__ float g_hb    [8192u  * 1024u];   // gate hidden

// ---------------- helpers ----------------
__device__ __forceinline__ float to_tf32(float x) {
    asm("cvt.rna.tf32.f32 %0, %1;" : "=f"(x) : "f"(x));
    return x;
}

__device__ __forceinline__ void mma_tf32(float* d, const float* a, const float* b) {
    const unsigned* A  = reinterpret_cast<const unsigned*>(a);
    const unsigned* Bv = reinterpret_cast<const unsigned*>(b);
    asm volatile(
        "mma.sync.aligned.m16n8k8.row.col.f32.tf32.tf32.f32 "
        "{%0,%1,%2,%3}, {%4,%5,%6,%7}, {%8,%9}, {%0,%1,%2,%3};"
        : "+f"(d[0]), "+f"(d[1]), "+f"(d[2]), "+f"(d[3])
        : "r"(A[0]), "r"(A[1]), "r"(A[2]), "r"(A[3]), "r"(Bv[0]), "r"(Bv[1]));
}

// ---------------- generic batched TF32 GEMM ----------------
// C[m,n] = scale * sum_k A[m,k] * B(n,k)   (+ bias[n]) (+ C_old if accum)
// BNT=true : B is row-major [N,K] (NT gemm, e.g. x @ W^T, Q@K^T)
// BNT=false: B is row-major [K,N] (NN gemm, e.g. attn @ V)
// Batch z -> (bI = z/H, hI = z%H); pointers offset by per-b / per-h strides.
// Requires: M % BM == 0, N % BN == 0, K % BK == 0 (guaranteed by call sites).
template<int BM, int BN, int BK, bool BNT>
__global__ void __launch_bounds__((BM/64)*(BN/32)*32)
gemm_tf32_kernel(const float* __restrict__ Abase, int lda, long long sAb, long long sAh,
                 const float* __restrict__ Bbase, int ldb, long long sBb, long long sBh,
                 float*       __restrict__ Cbase, int ldc, long long sCb, long long sCh,
                 int K, int H,
                 const float* __restrict__ bias, float scale, int accum)
{
    constexpr int WM = BM / 64;
    constexpr int WN = BN / 32;
    constexpr int NTHREADS = WM * WN * 32;

    const int z  = blockIdx.z;
    const int bI = z / H;
    const int hI = z - bI * H;
    const float* A  = Abase + (long long)bI * sAb + (long long)hI * sAh;
    const float* Bm = Bbase + (long long)bI * sBb + (long long)hI * sBh;
    float*       C  = Cbase + (long long)bI * sCb + (long long)hI * sCh;

    const int bm = blockIdx.y * BM;
    const int bn = blockIdx.x * BN;

    __shared__ float As[BM][BK + 1];
    __shared__ float Bs[BN][BK + 1];

    const int tid  = threadIdx.x;
    const int warp = tid >> 5;
    const int lane = tid & 31;
    const int gid  = lane >> 2;   // 0..7
    const int tig  = lane & 3;    // 0..3
    const int wm   = (warp % WM) * 64;
    const int wn   = (warp / WM) * 32;

    float acc[4][4][4];
    #pragma unroll
    for (int mi = 0; mi < 4; mi++)
        #pragma unroll
        for (int ni = 0; ni < 4; ni++)
            #pragma unroll
            for (int j = 0; j < 4; j++) acc[mi][ni][j] = 0.f;

    for (int k0 = 0; k0 < K; k0 += BK) {
        // load A tile [BM, BK]
        #pragma unroll 4
        for (int i = tid; i < BM * BK; i += NTHREADS) {
            int r = i / BK, c = i - r * BK;
            As[r][c] = to_tf32(A[(long long)(bm + r) * lda + (k0 + c)]);
        }
        // load B tile into [BN][BK] (n-major, k contiguous)
        if (BNT) {
            #pragma unroll 4
            for (int i = tid; i < BN * BK; i += NTHREADS) {
                int r = i / BK, c = i - r * BK;
                Bs[r][c] = to_tf32(Bm[(long long)(bn + r) * ldb + (k0 + c)]);
            }
        } else {
            #pragma unroll 4
            for (int i = tid; i < BN * BK; i += NTHREADS) {
                int n = i % BN, k = i / BN;  // coalesced along n
                Bs[n][k] = to_tf32(Bm[(long long)(k0 + k) * ldb + (bn + n)]);
            }
        }
        __syncthreads();

        #pragma unroll
        for (int kk = 0; kk < BK; kk += 8) {
            float af[4][4];
            float bf[4][2];
            #pragma unroll
            for (int mi = 0; mi < 4; mi++) {
                int r = wm + mi * 16 + gid;
                af[mi][0] = As[r    ][kk + tig];
                af[mi][1] = As[r + 8][kk + tig];
                af[mi][2] = As[r    ][kk + tig + 4];
                af[mi][3] = As[r + 8][kk + tig + 4];
            }
            #pragma unroll
            for (int ni = 0; ni < 4; ni++) {
                int c = wn + ni * 8 + gid;
                bf[ni][0] = Bs[c][kk + tig];
                bf[ni][1] = Bs[c][kk + tig + 4];
            }
            #pragma unroll
            for (int mi = 0; mi < 4; mi++)
                #pragma unroll
                for (int ni = 0; ni < 4; ni++)
                    mma_tf32(acc[mi][ni], af[mi], bf[ni]);
        }
        __syncthreads();
    }

    // epilogue
    #pragma unroll
    for (int mi = 0; mi < 4; mi++) {
        #pragma unroll
        for (int ni = 0; ni < 4; ni++) {
            int r0 = bm + wm + mi * 16 + gid;
            int c0 = bn + wn + ni * 8 + tig * 2;
            #pragma unroll
            for (int j = 0; j < 4; j++) {
                int r = r0 + ((j >= 2) ? 8 : 0);
                int c = c0 + (j & 1);
                float v = acc[mi][ni][j] * scale;
                if (bias)  v += bias[c];
                long long idx = (long long)r * ldc + c;
                if (accum) v += C[idx];
                C[idx] = v;
            }
        }
    }
}

// ---------------- softmax over rows ----------------
__global__ void softmax_kernel(float* __restrict__ x, int L)
{
    const long long base = (long long)blockIdx.x * L;
    const int tid = threadIdx.x, warp = tid >> 5, lane = tid & 31;
    __shared__ float red[8];
    __shared__ float bmax, bsum;

    float m = -1e30f;
    for (int i = tid; i < L; i += 256) m = fmaxf(m, x[base + i]);
    #pragma unroll
    for (int o = 16; o; o >>= 1) m = fmaxf(m, __shfl_xor_sync(0xffffffffu, m, o));
    if (lane == 0) red[warp] = m;
    __syncthreads();
    if (tid == 0) {
        float mm = red[0];
        #pragma unroll
        for (int i = 1; i < 8; i++) mm = fmaxf(mm, red[i]);
        bmax = mm;
    }
    __syncthreads();
    m = bmax;

    float s = 0.f;
    for (int i = tid; i < L; i += 256) {
        float e = __expf(x[base + i] - m);
        x[base + i] = e;
        s += e;
    }
    #pragma unroll
    for (int o = 16; o; o >>= 1) s += __shfl_xor_sync(0xffffffffu, s, o);
    __syncthreads();                 // protect red reuse
    if (lane == 0) red[warp] = s;
    __syncthreads();
    if (tid == 0) {
        float t = 0.f;
        #pragma unroll
        for (int i = 0; i < 8; i++) t += red[i];
        bsum = 1.f / t;
    }
    __syncthreads();
    float inv = bsum;
    for (int i = tid; i < L; i += 256) x[base + i] *= inv;
}

// ---------------- mean over heads (cross attn only) ----------------
// sc [B,16,P,S] -> out [B,P,S]
__global__ void attn_mean_kernel(const float* __restrict__ sc, float* __restrict__ out)
{
    long long idx = (long long)blockIdx.x * blockDim.x + threadIdx.x; // < 16*512*1024
    int s = (int)(idx & 1023);
    long long t = idx >> 10;
    int p = (int)(t & 511);
    int b = (int)(t >> 9);
    const float* base = sc + (long long)b * (16LL * 512 * 1024) + (long long)p * 1024 + s;
    float a = 0.f;
    #pragma unroll
    for (int h = 0; h < 16; h++) a += base[(long long)h * (512 * 1024)];
    out[idx] = a * (1.f / 16.f);
}

// ---------------- residual add + LayerNorm (row = 1024) ----------------
__global__ void add_ln_kernel(const float* __restrict__ x, const float* __restrict__ r,
                              const float* __restrict__ g, const float* __restrict__ bt,
                              float* __restrict__ out)
{
    const int row = blockIdx.x, tid = threadIdx.x;
    const long long base = (long long)row * 1024;
    __shared__ float ss[8], sq[8];
    __shared__ float smu, srs;

    float v[4];
    float s = 0.f, q = 0.f;
    #pragma unroll
    for (int j = 0; j < 4; j++) {
        int i = tid + j * 256;
        float t = x[base + i] + r[base + i];
        v[j] = t;
        s += t;
        q += t * t;
    }
    #pragma unroll
    for (int o = 16; o; o >>= 1) {
        s += __shfl_xor_sync(0xffffffffu, s, o);
        q += __shfl_xor_sync(0xffffffffu, q, o);
    }
    int warp = tid >> 5;
    if ((tid & 31) == 0) { ss[warp] = s; sq[warp] = q; }
    __syncthreads();
    if (tid == 0) {
        float S = 0.f, Q = 0.f;
        #pragma unroll
        for (int i = 0; i < 8; i++) { S += ss[i]; Q += sq[i]; }
        float mu  = S * (1.f / 1024.f);
        float var = Q * (1.f / 1024.f) - mu * mu;
        smu = mu;
        srs = rsqrtf(var + 1e-5f);
    }
    __syncthreads();
    float mu = smu, rs = srs;
    #pragma unroll
    for (int j = 0; j < 4; j++) {
        int i = tid + j * 256;
        out[base + i] = (v[j] - mu) * rs * g[i] + bt[i];
    }
}

// ---------------- exact GELU (erf) ----------------
__global__ void gelu_kernel(float* __restrict__ x, int n)
{
    int i = blockIdx.x * blockDim.x + threadIdx.x;
    if (i < n) {
        float v = x[i];
        x[i] = 0.5f * v * (1.f + erff(v * 0.7071067811865476f));
    }
}

// ---------------- gate logits + softmax(3) + weighted combine ----------------
__global__ void gate_combine_kernel(const float* __restrict__ h,
                                    const float* __restrict__ w2, const float* __restrict__ b2,
                                    const float* __restrict__ s0, const float* __restrict__ s1,
                                    const float* __restrict__ s2, float* __restrict__ out)
{
    const int row = blockIdx.x, tid = threadIdx.x;
    const long long base = (long long)row * 1024;
    __shared__ float r0[4], r1[4], r2[4];
    __shared__ float w[3];

    float p0 = 0.f, p1 = 0.f, p2 = 0.f;
    for (int i = tid; i < 1024; i += 128) {
        float v = h[base + i];
        p0 += v * w2[i];
        p1 += v * w2[1024 + i];
        p2 += v * w2[2048 + i];
    }
    #pragma unroll
    for (int o = 16; o; o >>= 1) {
        p0 += __shfl_xor_sync(0xffffffffu, p0, o);
        p1 += __shfl_xor_sync(0xffffffffu, p1, o);
        p2 += __shfl_xor_sync(0xffffffffu, p2, o);
    }
    int warp = tid >> 5;
    if ((tid & 31) == 0) { r0[warp] = p0; r1[warp] = p1; r2[warp] = p2; }
    __syncthreads();
    if (tid == 0) {
        float l0 = r0[0] + r0[1] + r0[2] + r0[3] + b2[0];
        float l1 = r1[0] + r1[1] + r1[2] + r1[3] + b2[1];
        float l2 = r2[0] + r2[1] + r2[2] + r2[3] + b2[2];
        float m  = fmaxf(l0, fmaxf(l1, l2));
        float e0 = __expf(l0 - m), e1 = __expf(l1 - m), e2 = __expf(l2 - m);
        float inv = 1.f / (e0 + e1 + e2);
        w[0] = e0 * inv; w[1] = e1 * inv; w[2] = e2 * inv;
    }
    __syncthreads();
    float w0 = w[0], w1 = w[1], w2v = w[2];
    for (int i = tid; i < 1024; i += 128)
        out[base + i] = w0 * s0[base + i] + w1 * s1[base + i] + w2v * s2[base + i];
}

// ---------------- launch ----------------
extern "C" void kernel_launch(void* const* d_in, const int* in_sizes, int n_in,
                              void* d_out, int out_size)
{
    (void)in_sizes; (void)n_in; (void)out_size;

    const float* proto = (const float*)d_in[0];
    const float* img   = (const float*)d_in[1];
    const float* cwi   = (const float*)d_in[2];
    const float* cbi   = (const float*)d_in[3];
    const float* cwo   = (const float*)d_in[4];
    const float* cbo   = (const float*)d_in[5];
    const float* swi   = (const float*)d_in[6];
    const float* sbi   = (const float*)d_in[7];
    const float* swo   = (const float*)d_in[8];
    const float* sbo   = (const float*)d_in[9];
    const float* lwi   = (const float*)d_in[10];
    const float* lbi   = (const float*)d_in[11];
    const float* lwo   = (const float*)d_in[12];
    const float* lbo   = (const float*)d_in[13];
    const float* n1g   = (const float*)d_in[14];
    const float* n1b   = (const float*)d_in[15];
    const float* n2g   = (const float*)d_in[16];
    const float* n2b   = (const float*)d_in[17];
    const float* n3g   = (const float*)d_in[18];
    const float* n3b   = (const float*)d_in[19];
    const float* gw1   = (const float*)d_in[20];
    const float* gb1   = (const float*)d_in[21];
    const float* gw2   = (const float*)d_in[22];
    const float* gb2   = (const float*)d_in[23];

    float* out_upd  = (float*)d_out;
    float* out_attn = (float*)d_out + 8388608;   // 16*512*1024

    float *q, *kv, *qkv, *sc, *ob, *rw, *cr, *se, *li, *hb;
    cudaGetSymbolAddress((void**)&q,   g_q);
    cudaGetSymbolAddress((void**)&kv,  g_kv);
    cudaGetSymbolAddress((void**)&qkv, g_qkv);
    cudaGetSymbolAddress((void**)&sc,  g_sc);
    cudaGetSymbolAddress((void**)&ob,  g_ob);
    cudaGetSymbolAddress((void**)&rw,  g_rw);
    cudaGetSymbolAddress((void**)&cr,  g_cross);
    cudaGetSymbolAddress((void**)&se,  g_selfo);
    cudaGetSymbolAddress((void**)&li,  g_light);
    cudaGetSymbolAddress((void**)&hb,  g_hb);

    // ============ cross attention (H=16, hd=64, kv_len=S=1024) ============
    // Q = proto @ wq^T + bq            [8192,1024]
    gemm_tf32_kernel<128,128,16,true><<<dim3(8,64,1),256>>>(
        proto,1024,0,0,  cwi,1024,0,0,  q,1024,0,0,  1024,1, cbi, 1.f, 0);
    // KV = img @ wkv^T + bkv           [16384,2048]
    gemm_tf32_kernel<128,128,16,true><<<dim3(16,128,1),256>>>(
        img,1024,0,0,  cwi+1048576,1024,0,0,  kv,2048,0,0,  1024,1, cbi+1024, 1.f, 0);
    // scores[b,h] = Qh @ Kh^T * 1/8    [512,1024] x 256
    gemm_tf32_kernel<128,128,16,true><<<dim3(8,4,256),256>>>(
        q,1024,524288LL,64LL,  kv,2048,2097152LL,64LL,
        sc,1024,8388608LL,524288LL,  64,16, nullptr, 0.125f, 0);
    softmax_kernel<<<131072,256>>>(sc, 1024);
    attn_mean_kernel<<<32768,256>>>(sc, out_attn);
    // O_h = attn @ V_h                 [512,64] x 256
    gemm_tf32_kernel<128,64,16,false><<<dim3(1,4,256),128>>>(
        sc,1024,8388608LL,524288LL,  kv+1024,2048,2097152LL,64LL,
        ob,1024,524288LL,64LL,  1024,16, nullptr, 1.f, 0);
    // out proj + residual LN
    gemm_tf32_kernel<128,128,16,true><<<dim3(8,64,1),256>>>(
        ob,1024,0,0,  cwo,1024,0,0,  rw,1024,0,0,  1024,1, cbo, 1.f, 0);
    add_ln_kernel<<<8192,256>>>(proto, rw, n1g, n1b, cr);

    // ============ self attention (H=16, hd=64, kv_len=512) ============
    gemm_tf32_kernel<128,128,16,true><<<dim3(24,64,1),256>>>(
        cr,1024,0,0,  swi,1024,0,0,  qkv,3072,0,0,  1024,1, sbi, 1.f, 0);
    gemm_tf32_kernel<128,128,16,true><<<dim3(4,4,256),256>>>(
        qkv,3072,1572864LL,64LL,  qkv+1024,3072,1572864LL,64LL,
        sc,512,4194304LL,262144LL,  64,16, nullptr, 0.125f, 0);
    softmax_kernel<<<131072,256>>>(sc, 512);
    gemm_tf32_kernel<128,64,16,false><<<dim3(1,4,256),128>>>(
        sc,512,4194304LL,262144LL,  qkv+2048,3072,1572864LL,64LL,
        ob,1024,524288LL,64LL,  512,16, nullptr, 1.f, 0);
    gemm_tf32_kernel<128,128,16,true><<<dim3(8,64,1),256>>>(
        ob,1024,0,0,  swo,1024,0,0,  rw,1024,0,0,  1024,1, sbo, 1.f, 0);
    add_ln_kernel<<<8192,256>>>(cr, rw, n2g, n2b, se);

    // ============ light attention (H=8, hd=128, kv_len=512) ============
    gemm_tf32_kernel<128,128,16,true><<<dim3(24,64,1),256>>>(
        se,1024,0,0,  lwi,1024,0,0,  qkv,3072,0,0,  1024,1, lbi, 1.f, 0);
    gemm_tf32_kernel<128,128,16,true><<<dim3(4,4,128),256>>>(
        qkv,3072,1572864LL,128LL,  qkv+1024,3072,1572864LL,128LL,
        sc,512,2097152LL,262144LL,  128,8, nullptr, 0.08838834764831845f, 0);
    softmax_kernel<<<65536,256>>>(sc, 512);
    gemm_tf32_kernel<128,128,16,false><<<dim3(1,4,128),256>>>(
        sc,512,2097152LL,262144LL,  qkv+2048,3072,1572864LL,128LL,
        ob,1024,524288LL,128LL,  512,8, nullptr, 1.f, 0);
    gemm_tf32_kernel<128,128,16,true><<<dim3(8,64,1),256>>>(
        ob,1024,0,0,  lwo,1024,0,0,  rw,1024,0,0,  1024,1, lbo, 1.f, 0);
    add_ln_kernel<<<8192,256>>>(se, rw, n3g, n3b, li);

    // ============ gate MLP: h = gelu([cr|se|li] @ gw1^T + gb1) ============
    gemm_tf32_kernel<128,128,16,true><<<dim3(8,64,1),256>>>(
        cr,1024,0,0,  gw1,      3072,0,0,  hb,1024,0,0,  1024,1, gb1,     1.f, 0);
    gemm_tf32_kernel<128,128,16,true><<<dim3(8,64,1),256>>>(
        se,1024,0,0,  gw1+1024, 3072,0,0,  hb,1024,0,0,  1024,1, nullptr, 1.f, 1);
    gemm_tf32_kernel<128,128,16,true><<<dim3(8,64,1),256>>>(
        li,1024,0,0,  gw1+2048, 3072,0,0,  hb,1024,0,0,  1024,1, nullptr, 1.f, 1);
    gelu_kernel<<<32768,256>>>(hb, 8388608);

    // ============ gate softmax(3) + combine -> updated ============
    gate_combine_kernel<<<8192,128>>>(hb, gw2, gb2, cr, se, li, out_upd);
}

// round 2
// speedup vs baseline: 2.2848x; 2.2848x over previous
#include <cuda_runtime.h>
#include <math.h>

// ---------------- problem constants ----------------
// B=16, P=512, S=1024, D=1024, H_FULL=16 (hd=64), H_LIGHT=8 (hd=128)

// ---------------- device scratch ----------------
__device__ float g_q     [8192u  * 1024u];
__device__ float g_kv    [16384u * 2048u];
__device__ float g_qkv   [8192u  * 3072u];
__device__ float g_sc    [134217728u];
__device__ float g_ob    [8192u  * 1024u];
__device__ float g_rw    [8192u  * 1024u];
__device__ float g_cross [8192u  * 1024u];
__device__ float g_selfo [8192u  * 1024u];
__device__ float g_light [8192u  * 1024u];
__device__ float g_hb    [8192u  * 1024u];

// ---------------- async copy helpers ----------------
__device__ __forceinline__ void cp_async16(void* smem, const void* gmem) {
    unsigned s = (unsigned)__cvta_generic_to_shared(smem);
    asm volatile("cp.async.cg.shared.global [%0], [%1], 16;\n" :: "r"(s), "l"(gmem));
}
__device__ __forceinline__ void cp_commit() { asm volatile("cp.async.commit_group;\n"); }
template<int N> __device__ __forceinline__ void cp_wait() {
    asm volatile("cp.async.wait_group %0;\n" :: "n"(N));
}

__device__ __forceinline__ void mma_tf32(float* d, const float* a, const float* b) {
    const unsigned* A  = reinterpret_cast<const unsigned*>(a);
    const unsigned* Bv = reinterpret_cast<const unsigned*>(b);
    asm volatile(
        "mma.sync.aligned.m16n8k8.row.col.f32.tf32.tf32.f32 "
        "{%0,%1,%2,%3}, {%4,%5,%6,%7}, {%8,%9}, {%0,%1,%2,%3};"
        : "+f"(d[0]), "+f"(d[1]), "+f"(d[2]), "+f"(d[3])
        : "r"(A[0]), "r"(A[1]), "r"(A[2]), "r"(A[3]), "r"(Bv[0]), "r"(Bv[1]));
}

// ---------------- pipelined batched TF32 GEMM ----------------
// C[m,n] = scale * sum_k A(m,k) * B(n,k)  (+ bias[n]) (GELU optional)
// BNT=true : B row-major [N,K];  BNT=false: B row-major [K,N]
// GATE=true: A is logical concat [A0|A1|A2] along k (each 1024 wide, lda=1024)
// NOTE: tf32 mma reads top 19 bits of f32 registers directly (no cvt needed).
template<int BM, int BN, int BK, bool BNT, bool GATE, bool GELU>
__global__ void __launch_bounds__((BM/64)*(BN/32)*32)
gemm2(const float* __restrict__ A0, const float* __restrict__ A1, const float* __restrict__ A2,
      int lda, long long sAb, long long sAh,
      const float* __restrict__ Bbase, int ldb, long long sBb, long long sBh,
      float*       __restrict__ Cbase, int ldc, long long sCb, long long sCh,
      int K, int H, const float* __restrict__ bias, float scale)
{
    constexpr int WM = BM / 64;
    constexpr int WN = BN / 32;
    constexpr int NTH = WM * WN * 32;
    constexpr int ASTR = BK + 4;                 // smem stride (floats), conflict-free
    constexpr int BSTR = BNT ? (BK + 4) : (BN + 8);
    constexpr int AEL  = BM * ASTR;
    constexpr int BEL  = BNT ? (BN * BSTR) : (BK * BSTR);

    extern __shared__ float sm[];
    float* As = sm;              // [2][BM][ASTR]
    float* Bs = sm + 2 * AEL;    // [2][..]

    const int z  = blockIdx.z;
    const int bI = z / H;
    const int hI = z - bI * H;
    const float* Abase = A0 + (long long)bI * sAb + (long long)hI * sAh;
    const float* Bm    = Bbase + (long long)bI * sBb + (long long)hI * sBh;
    float*       C     = Cbase + (long long)bI * sCb + (long long)hI * sCh;

    const int bm = blockIdx.y * BM;
    const int bn = blockIdx.x * BN;
    const int tid  = threadIdx.x;
    const int warp = tid >> 5;
    const int lane = tid & 31;
    const int gid  = lane >> 2;
    const int tig  = lane & 3;
    const int wm   = (warp % WM) * 64;
    const int wn   = (warp / WM) * 32;

    float acc[4][4][4] = {};

    auto loadA = [&](int buf, int k0) {
        const float* Ab;
        if (GATE) {
            Ab = (k0 < 1024) ? (A0 + k0)
               : (k0 < 2048) ? (A1 + (k0 - 1024))
                             : (A2 + (k0 - 2048));
        } else {
            Ab = Abase + k0;
        }
        #pragma unroll
        for (int i = tid; i < BM * BK / 4; i += NTH) {
            int r = i / (BK / 4), c = i % (BK / 4);
            cp_async16(&As[buf * AEL + r * ASTR + c * 4],
                       Ab + (long long)(bm + r) * lda + c * 4);
        }
    };
    auto loadB = [&](int buf, int k0) {
        if (BNT) {
            #pragma unroll
            for (int i = tid; i < BN * BK / 4; i += NTH) {
                int r = i / (BK / 4), c = i % (BK / 4);
                cp_async16(&Bs[buf * BEL + r * BSTR + c * 4],
                           Bm + (long long)(bn + r) * ldb + k0 + c * 4);
            }
        } else {
            #pragma unroll
            for (int i = tid; i < BK * BN / 4; i += NTH) {
                int kr = i / (BN / 4), c = i % (BN / 4);
                cp_async16(&Bs[buf * BEL + kr * BSTR + c * 4],
                           Bm + (long long)(k0 + kr) * ldb + bn + c * 4);
            }
        }
    };
    auto compute = [&](int buf) {
        const float* Ab  = As + buf * AEL;
        const float* Bb2 = Bs + buf * BEL;
        #pragma unroll
        for (int kk = 0; kk < BK; kk += 8) {
            float af[4][4], bf[4][2];
            #pragma unroll
            for (int mi = 0; mi < 4; mi++) {
                int r = wm + mi * 16 + gid;
                af[mi][0] = Ab[r * ASTR + kk + tig];
                af[mi][1] = Ab[(r + 8) * ASTR + kk + tig];
                af[mi][2] = Ab[r * ASTR + kk + tig + 4];
                af[mi][3] = Ab[(r + 8) * ASTR + kk + tig + 4];
            }
            #pragma unroll
            for (int ni = 0; ni < 4; ni++) {
                int c = wn + ni * 8 + gid;
                if (BNT) {
                    bf[ni][0] = Bb2[c * BSTR + kk + tig];
                    bf[ni][1] = Bb2[c * BSTR + kk + tig + 4];
                } else {
                    bf[ni][0] = Bb2[(kk + tig) * BSTR + c];
                    bf[ni][1] = Bb2[(kk + tig + 4) * BSTR + c];
                }
            }
            #pragma unroll
            for (int mi = 0; mi < 4; mi++)
                #pragma unroll
                for (int ni = 0; ni < 4; ni++)
                    mma_tf32(acc[mi][ni], af[mi], bf[ni]);
        }
    };

    const int T = K / BK;
    loadA(0, 0); loadB(0, 0); cp_commit();
    for (int t = 0; t < T; t++) {
        if (t + 1 < T) {
            loadA((t + 1) & 1, (t + 1) * BK);
            loadB((t + 1) & 1, (t + 1) * BK);
            cp_commit();
            cp_wait<1>();
        } else {
            cp_wait<0>();
        }
        __syncthreads();
        compute(t & 1);
        __syncthreads();
    }

    // epilogue
    #pragma unroll
    for (int mi = 0; mi < 4; mi++) {
        #pragma unroll
        for (int ni = 0; ni < 4; ni++) {
            int r0 = bm + wm + mi * 16 + gid;
            int c0 = bn + wn + ni * 8 + tig * 2;
            #pragma unroll
            for (int j = 0; j < 4; j++) {
                int r = r0 + ((j >= 2) ? 8 : 0);
                int c = c0 + (j & 1);
                float v = acc[mi][ni][j] * scale;
                if (bias) v += bias[c];
                if (GELU) v = 0.5f * v * (1.f + erff(v * 0.7071067811865476f));
                C[(long long)r * ldc + c] = v;
            }
        }
    }
}

// ---------------- warp-per-row softmax (register-resident) ----------------
template<int L>
__global__ void softmax_w(float* __restrict__ x)
{
    constexpr int NV = L / 128;      // float4 per lane
    const int warp = threadIdx.x >> 5, lane = threadIdx.x & 31;
    const long long row = (long long)blockIdx.x * 8 + warp;
    float* p = x + row * (long long)L;

    float4 v[NV];
    float m = -1e30f;
    #pragma unroll
    for (int j = 0; j < NV; j++) {
        v[j] = *(const float4*)(p + lane * 4 + j * 128);
        m = fmaxf(m, fmaxf(fmaxf(v[j].x, v[j].y), fmaxf(v[j].z, v[j].w)));
    }
    #pragma unroll
    for (int o = 16; o; o >>= 1) m = fmaxf(m, __shfl_xor_sync(0xffffffffu, m, o));

    float s = 0.f;
    #pragma unroll
    for (int j = 0; j < NV; j++) {
        v[j].x = __expf(v[j].x - m);
        v[j].y = __expf(v[j].y - m);
        v[j].z = __expf(v[j].z - m);
        v[j].w = __expf(v[j].w - m);
        s += v[j].x + v[j].y + v[j].z + v[j].w;
    }
    #pragma unroll
    for (int o = 16; o; o >>= 1) s += __shfl_xor_sync(0xffffffffu, s, o);
    float inv = 1.f / s;
    #pragma unroll
    for (int j = 0; j < NV; j++) {
        v[j].x *= inv; v[j].y *= inv; v[j].z *= inv; v[j].w *= inv;
        *(float4*)(p + lane * 4 + j * 128) = v[j];
    }
}

// ---------------- mean over heads (cross attn), float4 ----------------
__global__ void attn_mean4(const float4* __restrict__ sc, float4* __restrict__ out)
{
    int idx = blockIdx.x * 256 + threadIdx.x;          // < 2097152
    int s4 = idx & 255;
    int t  = idx >> 8;
    int p  = t & 511;
    int b  = t >> 9;
    const float4* base = sc + (long long)b * (16LL * 512 * 256) + (long long)p * 256 + s4;
    float4 a = make_float4(0.f, 0.f, 0.f, 0.f);
    #pragma unroll
    for (int h = 0; h < 16; h++) {
        float4 v = base[(long long)h * (512 * 256)];
        a.x += v.x; a.y += v.y; a.z += v.z; a.w += v.w;
    }
    const float k = 1.f / 16.f;
    a.x *= k; a.y *= k; a.z *= k; a.w *= k;
    out[idx] = a;
}

// ---------------- residual add + LayerNorm (row = 1024), float4 ----------------
__global__ void add_ln4(const float4* __restrict__ x, const float4* __restrict__ r,
                        const float4* __restrict__ g, const float4* __restrict__ bt,
                        float4* __restrict__ out)
{
    const int row = blockIdx.x, tid = threadIdx.x;
    const long long base = (long long)row * 256;
    __shared__ float ss[8], sq[8];
    __shared__ float smu, srs;

    float4 xv = x[base + tid], rv = r[base + tid];
    float4 v = make_float4(xv.x + rv.x, xv.y + rv.y, xv.z + rv.z, xv.w + rv.w);
    float s = v.x + v.y + v.z + v.w;
    float q = v.x * v.x + v.y * v.y + v.z * v.z + v.w * v.w;
    #pragma unroll
    for (int o = 16; o; o >>= 1) {
        s += __shfl_xor_sync(0xffffffffu, s, o);
        q += __shfl_xor_sync(0xffffffffu, q, o);
    }
    const int warp = tid >> 5;
    if ((tid & 31) == 0) { ss[warp] = s; sq[warp] = q; }
    __syncthreads();
    if (tid == 0) {
        float S = 0.f, Q = 0.f;
        #pragma unroll
        for (int i = 0; i < 8; i++) { S += ss[i]; Q += sq[i]; }
        float mu  = S * (1.f / 1024.f);
        float var = Q * (1.f / 1024.f) - mu * mu;
        smu = mu;
        srs = rsqrtf(var + 1e-5f);
    }
    __syncthreads();
    float mu = smu, rs = srs;
    float4 gv = g[tid], bv = bt[tid];
    out[base + tid] = make_float4((v.x - mu) * rs * gv.x + bv.x,
                                  (v.y - mu) * rs * gv.y + bv.y,
                                  (v.z - mu) * rs * gv.z + bv.z,
                                  (v.w - mu) * rs * gv.w + bv.w);
}

// ---------------- gate logits + softmax(3) + combine, float4 ----------------
__global__ void gate_combine4(const float4* __restrict__ h,
                              const float4* __restrict__ w2, const float* __restrict__ b2,
                              const float4* __restrict__ s0, const float4* __restrict__ s1,
                              const float4* __restrict__ s2, float4* __restrict__ out)
{
    const int row = blockIdx.x, tid = threadIdx.x;
    const long long base = (long long)row * 256;
    __shared__ float r0[8], r1[8], r2[8];
    __shared__ float w[3];

    float4 hv = h[base + tid];
    float4 wa = w2[tid], wb = w2[256 + tid], wc = w2[512 + tid];
    float p0 = hv.x * wa.x + hv.y * wa.y + hv.z * wa.z + hv.w * wa.w;
    float p1 = hv.x * wb.x + hv.y * wb.y + hv.z * wb.z + hv.w * wb.w;
    float p2 = hv.x * wc.x + hv.y * wc.y + hv.z * wc.z + hv.w * wc.w;
    #pragma unroll
    for (int o = 16; o; o >>= 1) {
        p0 += __shfl_xor_sync(0xffffffffu, p0, o);
        p1 += __shfl_xor_sync(0xffffffffu, p1, o);
        p2 += __shfl_xor_sync(0xffffffffu, p2, o);
    }
    const int warp = tid >> 5;
    if ((tid & 31) == 0) { r0[warp] = p0; r1[warp] = p1; r2[warp] = p2; }
    __syncthreads();
    if (tid == 0) {
        float l0 = b2[0], l1 = b2[1], l2 = b2[2];
        #pragma unroll
        for (int i = 0; i < 8; i++) { l0 += r0[i]; l1 += r1[i]; l2 += r2[i]; }
        float m  = fmaxf(l0, fmaxf(l1, l2));
        float e0 = __expf(l0 - m), e1 = __expf(l1 - m), e2 = __expf(l2 - m);
        float inv = 1.f / (e0 + e1 + e2);
        w[0] = e0 * inv; w[1] = e1 * inv; w[2] = e2 * inv;
    }
    __syncthreads();
    float w0 = w[0], w1 = w[1], w2v = w[2];
    float4 a = s0[base + tid], b = s1[base + tid], c = s2[base + tid];
    out[base + tid] = make_float4(w0 * a.x + w1 * b.x + w2v * c.x,
                                  w0 * a.y + w1 * b.y + w2v * c.y,
                                  w0 * a.z + w1 * b.z + w2v * c.z,
                                  w0 * a.w + w1 * b.w + w2v * c.w);
}

// ---------------- launch ----------------
extern "C" void kernel_launch(void* const* d_in, const int* in_sizes, int n_in,
                              void* d_out, int out_size)
{
    (void)in_sizes; (void)n_in; (void)out_size;

    const float* proto = (const float*)d_in[0];
    const float* img   = (const float*)d_in[1];
    const float* cwi   = (const float*)d_in[2];
    const float* cbi   = (const float*)d_in[3];
    const float* cwo   = (const float*)d_in[4];
    const float* cbo   = (const float*)d_in[5];
    const float* swi   = (const float*)d_in[6];
    const float* sbi   = (const float*)d_in[7];
    const float* swo   = (const float*)d_in[8];
    const float* sbo   = (const float*)d_in[9];
    const float* lwi   = (const float*)d_in[10];
    const float* lbi   = (const float*)d_in[11];
    const float* lwo   = (const float*)d_in[12];
    const float* lbo   = (const float*)d_in[13];
    const float* n1g   = (const float*)d_in[14];
    const float* n1b   = (const float*)d_in[15];
    const float* n2g   = (const float*)d_in[16];
    const float* n2b   = (const float*)d_in[17];
    const float* n3g   = (const float*)d_in[18];
    const float* n3b   = (const float*)d_in[19];
    const float* gw1   = (const float*)d_in[20];
    const float* gb1   = (const float*)d_in[21];
    const float* gw2   = (const float*)d_in[22];
    const float* gb2   = (const float*)d_in[23];

    float* out_upd  = (float*)d_out;
    float* out_attn = (float*)d_out + 8388608;

    float *q, *kv, *qkv, *sc, *ob, *rw, *cr, *se, *li, *hb;
    cudaGetSymbolAddress((void**)&q,   g_q);
    cudaGetSymbolAddress((void**)&kv,  g_kv);
    cudaGetSymbolAddress((void**)&qkv, g_qkv);
    cudaGetSymbolAddress((void**)&sc,  g_sc);
    cudaGetSymbolAddress((void**)&ob,  g_ob);
    cudaGetSymbolAddress((void**)&rw,  g_rw);
    cudaGetSymbolAddress((void**)&cr,  g_cross);
    cudaGetSymbolAddress((void**)&se,  g_selfo);
    cudaGetSymbolAddress((void**)&li,  g_light);
    cudaGetSymbolAddress((void**)&hb,  g_hb);

    constexpr size_t SM_NT    = (2 * 128 * 36 + 2 * 128 * 36) * 4;   // 73728
    constexpr size_t SM_NN64  = (2 * 128 * 36 + 2 * 32 * 72)  * 4;   // 55296
    constexpr size_t SM_NN128 = (2 * 128 * 36 + 2 * 32 * 136) * 4;   // 71680

    cudaFuncSetAttribute((const void*)gemm2<128,128,32,true,false,false>,
                         cudaFuncAttributeMaxDynamicSharedMemorySize, SM_NT);
    cudaFuncSetAttribute((const void*)gemm2<128,128,32,true,true,true>,
                         cudaFuncAttributeMaxDynamicSharedMemorySize, SM_NT);
    cudaFuncSetAttribute((const void*)gemm2<128,64,32,false,false,false>,
                         cudaFuncAttributeMaxDynamicSharedMemorySize, SM_NN64);
    cudaFuncSetAttribute((const void*)gemm2<128,128,32,false,false,false>,
                         cudaFuncAttributeMaxDynamicSharedMemorySize, SM_NN128);

    // ============ cross attention (H=16, hd=64, kv=1024) ============
    gemm2<128,128,32,true,false,false><<<dim3(8,64,1),256,SM_NT>>>(
        proto,nullptr,nullptr,1024,0,0,  cwi,1024,0,0,  q,1024,0,0,  1024,1, cbi, 1.f);
    gemm2<128,128,32,true,false,false><<<dim3(16,128,1),256,SM_NT>>>(
        img,nullptr,nullptr,1024,0,0,  cwi+1048576,1024,0,0,  kv,2048,0,0,  1024,1, cbi+1024, 1.f);
    gemm2<128,128,32,true,false,false><<<dim3(8,4,256),256,SM_NT>>>(
        q,nullptr,nullptr,1024,524288LL,64LL,  kv,2048,2097152LL,64LL,
        sc,1024,8388608LL,524288LL,  64,16, nullptr, 0.125f);
    softmax_w<1024><<<16384,256>>>(sc);
    attn_mean4<<<8192,256>>>((const float4*)sc, (float4*)out_attn);
    gemm2<128,64,32,false,false,false><<<dim3(1,4,256),128,SM_NN64>>>(
        sc,nullptr,nullptr,1024,8388608LL,524288LL,  kv+1024,2048,2097152LL,64LL,
        ob,1024,524288LL,64LL,  1024,16, nullptr, 1.f);
    gemm2<128,128,32,true,false,false><<<dim3(8,64,1),256,SM_NT>>>(
        ob,nullptr,nullptr,1024,0,0,  cwo,1024,0,0,  rw,1024,0,0,  1024,1, cbo, 1.f);
    add_ln4<<<8192,256>>>((const float4*)proto,(const float4*)rw,
                          (const float4*)n1g,(const float4*)n1b,(float4*)cr);

    // ============ self attention (H=16, hd=64, kv=512) ============
    gemm2<128,128,32,true,false,false><<<dim3(24,64,1),256,SM_NT>>>(
        cr,nullptr,nullptr,1024,0,0,  swi,1024,0,0,  qkv,3072,0,0,  1024,1, sbi, 1.f);
    gemm2<128,128,32,true,false,false><<<dim3(4,4,256),256,SM_NT>>>(
        qkv,nullptr,nullptr,3072,1572864LL,64LL,  qkv+1024,3072,1572864LL,64LL,
        sc,512,4194304LL,262144LL,  64,16, nullptr, 0.125f);
    softmax_w<512><<<16384,256>>>(sc);
    gemm2<128,64,32,false,false,false><<<dim3(1,4,256),128,SM_NN64>>>(
        sc,nullptr,nullptr,512,4194304LL,262144LL,  qkv+2048,3072,1572864LL,64LL,
        ob,1024,524288LL,64LL,  512,16, nullptr, 1.f);
    gemm2<128,128,32,true,false,false><<<dim3(8,64,1),256,SM_NT>>>(
        ob,nullptr,nullptr,1024,0,0,  swo,1024,0,0,  rw,1024,0,0,  1024,1, sbo, 1.f);
    add_ln4<<<8192,256>>>((const float4*)cr,(const float4*)rw,
                          (const float4*)n2g,(const float4*)n2b,(float4*)se);

    // ============ light attention (H=8, hd=128, kv=512) ============
    gemm2<128,128,32,true,false,false><<<dim3(24,64,1),256,SM_NT>>>(
        se,nullptr,nullptr,1024,0,0,  lwi,1024,0,0,  qkv,3072,0,0,  1024,1, lbi, 1.f);
    gemm2<128,128,32,true,false,false><<<dim3(4,4,128),256,SM_NT>>>(
        qkv,nullptr,nullptr,3072,1572864LL,128LL,  qkv+1024,3072,1572864LL,128LL,
        sc,512,2097152LL,262144LL,  128,8, nullptr, 0.08838834764831845f);
    softmax_w<512><<<8192,256>>>(sc);
    gemm2<128,128,32,false,false,false><<<dim3(1,4,128),256,SM_NN128>>>(
        sc,nullptr,nullptr,512,2097152LL,262144LL,  qkv+2048,3072,1572864LL,128LL,
        ob,1024,524288LL,128LL,  512,8, nullptr, 1.f);
    gemm2<128,128,32,true,false,false><<<dim3(8,64,1),256,SM_NT>>>(
        ob,nullptr,nullptr,1024,0,0,  lwo,1024,0,0,  rw,1024,0,0,  1024,1, lbo, 1.f);
    add_ln4<<<8192,256>>>((const float4*)se,(const float4*)rw,
                          (const float4*)n3g,(const float4*)n3b,(float4*)li);

    // ============ gate MLP (single K=3072 GEMM, GELU fused) ============
    gemm2<128,128,32,true,true,true><<<dim3(8,64,1),256,SM_NT>>>(
        cr,se,li,1024,0,0,  gw1,3072,0,0,  hb,1024,0,0,  3072,1, gb1, 1.f);

    // ============ gate softmax(3) + combine ============
    gate_combine4<<<8192,256>>>((const float4*)hb,(const float4*)gw2,gb2,
                                (const float4*)cr,(const float4*)se,(const float4*)li,
                                (float4*)out_upd);
}